// round 7
// baseline (speedup 1.0000x reference)
#include <cuda_runtime.h>
#include <math.h>

#define BATCH 8
#define TQ 1024
#define TM 1024
#define DIM 512
#define ATTND 512
#define NH 8
#define HD 64
#define NEG_INF_F (-4294967295.0f)

// Scratch for projected Q/K/V (static __device__ arrays: allowed, no runtime alloc)
__device__ float g_Q[(size_t)BATCH * TQ * ATTND];
__device__ float g_K[(size_t)BATCH * TM * ATTND];
__device__ float g_V[(size_t)BATCH * TM * ATTND];

// ---------------------------------------------------------------------------
// SGEMM: C[M,512] = A[M,512] @ W[512,512], fp32, 128x128 tile, kt=8, 8x8 micro
// ---------------------------------------------------------------------------
__global__ __launch_bounds__(256) void sgemm_k512(
    const float* __restrict__ A, const float* __restrict__ W, float* __restrict__ C)
{
    __shared__ float As[8][128];
    __shared__ float Bs[8][128];

    const int t  = threadIdx.x;
    const int tx = t & 15;        // 16 col groups (8 cols each)
    const int ty = t >> 4;        // 16 row groups (8 rows each)
    const int m0 = blockIdx.y * 128;
    const int n0 = blockIdx.x * 128;

    const int lrow = t >> 1, lseg = t & 1;   // A loader: 128 rows x 2 float4
    const int lkk  = t >> 5, lsg  = t & 31;  // W loader: 8 k-rows x 32 float4

    float acc[8][8];
#pragma unroll
    for (int i = 0; i < 8; i++)
#pragma unroll
        for (int j = 0; j < 8; j++) acc[i][j] = 0.f;

    for (int k0 = 0; k0 < 512; k0 += 8) {
        float4 av = *(const float4*)&A[(size_t)(m0 + lrow) * 512 + k0 + lseg * 4];
        As[lseg * 4 + 0][lrow] = av.x;
        As[lseg * 4 + 1][lrow] = av.y;
        As[lseg * 4 + 2][lrow] = av.z;
        As[lseg * 4 + 3][lrow] = av.w;
        *(float4*)&Bs[lkk][lsg * 4] =
            *(const float4*)&W[(size_t)(k0 + lkk) * 512 + n0 + lsg * 4];
        __syncthreads();
#pragma unroll
        for (int kk = 0; kk < 8; kk++) {
            float a[8], bb[8];
#pragma unroll
            for (int i = 0; i < 8; i++) a[i] = As[kk][ty * 8 + i];
            float4 b0 = *(float4*)&Bs[kk][tx * 8];
            float4 b1 = *(float4*)&Bs[kk][tx * 8 + 4];
            bb[0] = b0.x; bb[1] = b0.y; bb[2] = b0.z; bb[3] = b0.w;
            bb[4] = b1.x; bb[5] = b1.y; bb[6] = b1.z; bb[7] = b1.w;
#pragma unroll
            for (int i = 0; i < 8; i++)
#pragma unroll
                for (int j = 0; j < 8; j++) acc[i][j] = fmaf(a[i], bb[j], acc[i][j]);
        }
        __syncthreads();
    }
#pragma unroll
    for (int i = 0; i < 8; i++) {
        float* crow = &C[(size_t)(m0 + ty * 8 + i) * 512 + n0 + tx * 8];
        *(float4*)&crow[0] = make_float4(acc[i][0], acc[i][1], acc[i][2], acc[i][3]);
        *(float4*)&crow[4] = make_float4(acc[i][4], acc[i][5], acc[i][6], acc[i][7]);
    }
}

// ---------------------------------------------------------------------------
// Fused attention per (b, h, 128-query tile):
//  phase 1: S = Q K^T * 0.125, mask (causal + lengths), online max/sum, raw S -> align
//  reduce : 16-lane shfl flash merge -> rowmax, 1/rowsum in smem
//  phase 3: P = exp(S-max)/sum (re-read S from L2), write P to align, ctx = P @ V
// ---------------------------------------------------------------------------
#define QS_STRIDE 65     // Qs/Ps row stride  (128 rows)
#define KT_STRIDE 132    // Kts row stride    (64 d rows x 128 keys)
#define VS_STRIDE 68     // Vs row stride     (64 m rows x 64 dims)

__global__ __launch_bounds__(256) void attn_kernel(
    const int* __restrict__ mem_len, const int* __restrict__ qry_len,
    float* __restrict__ ctx_out, float* __restrict__ align_out)
{
    extern __shared__ float sm[];
    float* Qs   = sm;                         // [128][65]  (reused as Ps)
    float* Kts  = sm + 128 * QS_STRIDE;       // [64][132]  (reused as Vs[64][68])
    float* rmax = Kts + 64 * KT_STRIDE;       // [128]
    float* rinv = rmax + 128;                 // [128]

    const int t  = threadIdx.x;
    const int tx = t & 15;
    const int ty = t >> 4;
    const int q0 = blockIdx.x * 128;
    const int h  = blockIdx.y;
    const int b  = blockIdx.z;

    const int mlen = mem_len[b];
    const int qlen = qry_len[b];

    const float* Qbase = g_Q + (size_t)b * TQ * ATTND + h * HD;
    const float* Kbase = g_K + (size_t)b * TM * ATTND + h * HD;
    const float* Vbase = g_V + (size_t)b * TM * ATTND + h * HD;
    float* arow = align_out + ((size_t)(b * NH + h)) * TQ * TM;

    // ---- load Q tile (128 x 64) ----
#pragma unroll
    for (int it = 0; it < 8; it++) {
        int idx = t + it * 256;             // 0..2047 float4s
        int r = idx >> 4, seg = idx & 15;
        float4 v = *(const float4*)&Qbase[(size_t)(q0 + r) * ATTND + seg * 4];
        float* dst = &Qs[r * QS_STRIDE + seg * 4];
        dst[0] = v.x; dst[1] = v.y; dst[2] = v.z; dst[3] = v.w;
    }

    float rm[8], rl[8];
#pragma unroll
    for (int i = 0; i < 8; i++) { rm[i] = -INFINITY; rl[i] = 0.f; }

    // ---- phase 1: logits over key tiles of 128 ----
    for (int k0 = 0; k0 < TM; k0 += 128) {
        __syncthreads();   // protect Kts reuse / Qs first use
        // load K tile transposed: Kts[d][key]
#pragma unroll
        for (int it = 0; it < 8; it++) {
            int idx = t + it * 256;
            int key = idx >> 4, seg = idx & 15;
            float4 v = *(const float4*)&Kbase[(size_t)(k0 + key) * ATTND + seg * 4];
            Kts[(seg * 4 + 0) * KT_STRIDE + key] = v.x;
            Kts[(seg * 4 + 1) * KT_STRIDE + key] = v.y;
            Kts[(seg * 4 + 2) * KT_STRIDE + key] = v.z;
            Kts[(seg * 4 + 3) * KT_STRIDE + key] = v.w;
        }
        __syncthreads();

        float s[8][8];
#pragma unroll
        for (int i = 0; i < 8; i++)
#pragma unroll
            for (int j = 0; j < 8; j++) s[i][j] = 0.f;

#pragma unroll
        for (int kk = 0; kk < 64; kk++) {
            float a[8], bb[8];
#pragma unroll
            for (int i = 0; i < 8; i++) a[i] = Qs[(ty * 8 + i) * QS_STRIDE + kk];
            float4 b0 = *(float4*)&Kts[kk * KT_STRIDE + tx * 8];
            float4 b1 = *(float4*)&Kts[kk * KT_STRIDE + tx * 8 + 4];
            bb[0] = b0.x; bb[1] = b0.y; bb[2] = b0.z; bb[3] = b0.w;
            bb[4] = b1.x; bb[5] = b1.y; bb[6] = b1.z; bb[7] = b1.w;
#pragma unroll
            for (int i = 0; i < 8; i++)
#pragma unroll
                for (int j = 0; j < 8; j++) s[i][j] = fmaf(a[i], bb[j], s[i][j]);
        }

        // mask + scale + store raw logits + online softmax state
#pragma unroll
        for (int i = 0; i < 8; i++) {
            const int q = q0 + ty * 8 + i;
            const bool qv = q < qlen;
            float vals[8];
#pragma unroll
            for (int j = 0; j < 8; j++) {
                int m = k0 + tx * 8 + j;
                bool ok = qv && (m <= q) && (m < mlen);
                vals[j] = ok ? s[i][j] * 0.125f : NEG_INF_F;
            }
            float* dst = &arow[(size_t)q * TM + k0 + tx * 8];
            *(float4*)&dst[0] = make_float4(vals[0], vals[1], vals[2], vals[3]);
            *(float4*)&dst[4] = make_float4(vals[4], vals[5], vals[6], vals[7]);

            float tmx = vals[0];
#pragma unroll
            for (int j = 1; j < 8; j++) tmx = fmaxf(tmx, vals[j]);
            float tsum = 0.f;
#pragma unroll
            for (int j = 0; j < 8; j++) tsum += __expf(vals[j] - tmx);
            float nm = fmaxf(rm[i], tmx);
            rl[i] = rl[i] * __expf(rm[i] - nm) + tsum * __expf(tmx - nm);
            rm[i] = nm;
        }
    }

    // ---- cross-tx flash merge (16 lanes per row group) ----
#pragma unroll
    for (int i = 0; i < 8; i++) {
        float m_ = rm[i], l_ = rl[i];
#pragma unroll
        for (int off = 8; off >= 1; off >>= 1) {
            float om = __shfl_xor_sync(0xffffffffu, m_, off, 16);
            float ol = __shfl_xor_sync(0xffffffffu, l_, off, 16);
            float nm = fmaxf(m_, om);
            l_ = l_ * __expf(m_ - nm) + ol * __expf(om - nm);
            m_ = nm;
        }
        if (tx == 0) {
            rmax[ty * 8 + i] = m_;
            rinv[ty * 8 + i] = 1.0f / l_;
        }
    }

    // ---- phase 3: normalized P (write back) + ctx = P @ V ----
    float* Ps = Qs;     // [128][65]
    float* Vs = Kts;    // [64][68]
    float ctx[8][4];
#pragma unroll
    for (int i = 0; i < 8; i++)
#pragma unroll
        for (int j = 0; j < 4; j++) ctx[i][j] = 0.f;

    for (int m0 = 0; m0 < TM; m0 += 64) {
        __syncthreads();   // buffers reuse + rmax/rinv visibility on first iter
        // load V tile [64][64]
#pragma unroll
        for (int it = 0; it < 4; it++) {
            int idx = t + it * 256;           // 0..1023 float4s
            int m = idx >> 4, seg = idx & 15;
            float4 v = *(const float4*)&Vbase[(size_t)(m0 + m) * ATTND + seg * 4];
            float* dst = &Vs[m * VS_STRIDE + seg * 4];
            dst[0] = v.x; dst[1] = v.y; dst[2] = v.z; dst[3] = v.w;
        }
        // compute P tile, write normalized probs back to align
#pragma unroll
        for (int n = 0; n < 32; n++) {
            int e = t + n * 256;              // 0..8191
            int r = e >> 6, m = e & 63;
            size_t gi = (size_t)(q0 + r) * TM + m0 + m;
            float sval = arow[gi];
            float p = __expf(sval - rmax[r]) * rinv[r];
            arow[gi] = p;
            Ps[r * QS_STRIDE + m] = p;
        }
        __syncthreads();
        // micro GEMM: ctx[128][64] += Ps[128][64] @ Vs[64][64]
#pragma unroll
        for (int m = 0; m < 64; m++) {
            float a[8];
#pragma unroll
            for (int i = 0; i < 8; i++) a[i] = Ps[(ty * 8 + i) * QS_STRIDE + m];
            float4 bv = *(float4*)&Vs[m * VS_STRIDE + tx * 4];
#pragma unroll
            for (int i = 0; i < 8; i++) {
                ctx[i][0] = fmaf(a[i], bv.x, ctx[i][0]);
                ctx[i][1] = fmaf(a[i], bv.y, ctx[i][1]);
                ctx[i][2] = fmaf(a[i], bv.z, ctx[i][2]);
                ctx[i][3] = fmaf(a[i], bv.w, ctx[i][3]);
            }
        }
    }

    // write contexts: (b, q, h*64 + d)
#pragma unroll
    for (int i = 0; i < 8; i++) {
        size_t off = (size_t)(b * TQ + q0 + ty * 8 + i) * ATTND + h * HD + tx * 4;
        *(float4*)&ctx_out[off] = make_float4(ctx[i][0], ctx[i][1], ctx[i][2], ctx[i][3]);
    }
}

// ---------------------------------------------------------------------------
extern "C" void kernel_launch(void* const* d_in, const int* in_sizes, int n_in,
                              void* d_out, int out_size)
{
    const float* inputs = (const float*)d_in[0];
    const float* memory = (const float*)d_in[1];
    const float* Wq     = (const float*)d_in[2];
    const float* Wk     = (const float*)d_in[3];
    const float* Wv     = (const float*)d_in[4];
    const int*   mlen   = (const int*)d_in[5];
    const int*   qlen   = (const int*)d_in[6];

    float* out   = (float*)d_out;
    float* ctx   = out;                                   // (B, TQ, ATTN)
    float* align = out + (size_t)BATCH * TQ * ATTND;      // (B, H, TQ, TM)

    float *Qb, *Kb, *Vb;
    cudaGetSymbolAddress((void**)&Qb, g_Q);
    cudaGetSymbolAddress((void**)&Kb, g_K);
    cudaGetSymbolAddress((void**)&Vb, g_V);

    // QKV projections: M = B*T = 8192
    dim3 ggrid(4, 64);
    sgemm_k512<<<ggrid, 256>>>(inputs, Wq, Qb);
    sgemm_k512<<<ggrid, 256>>>(memory, Wk, Kb);
    sgemm_k512<<<ggrid, 256>>>(memory, Wv, Vb);

    // fused attention
    const int smem_bytes = (128 * QS_STRIDE + 64 * KT_STRIDE + 256) * sizeof(float);
    cudaFuncSetAttribute(attn_kernel, cudaFuncAttributeMaxDynamicSharedMemorySize,
                         smem_bytes);
    dim3 agrid(TQ / 128, NH, BATCH);
    attn_kernel<<<agrid, 256, smem_bytes>>>(mlen, qlen, ctx, align);
}

// round 9
// speedup vs baseline: 2.4838x; 2.4838x over previous
#include <cuda_runtime.h>
#include <cuda_bf16.h>
#include <math.h>
#include <stdint.h>

#define NEG_INF_F (-4294967295.0f)
#define NELEM (8 * 1024 * 512)

// ---------------------------------------------------------------------------
// Static device scratch (bf16 hi/lo split arrays)
// ---------------------------------------------------------------------------
__device__ __nv_bfloat16 g_Ihi[NELEM], g_Ilo[NELEM];     // inputs split
__device__ __nv_bfloat16 g_Mhi[NELEM], g_Mlo[NELEM];     // memory split
__device__ __nv_bfloat16 g_Qhi[NELEM], g_Qlo[NELEM];
__device__ __nv_bfloat16 g_Khi[NELEM], g_Klo[NELEM];
__device__ __nv_bfloat16 g_Vhi[NELEM], g_Vlo[NELEM];
__device__ __nv_bfloat16 g_Wqh[512*512], g_Wql[512*512]; // W^T split [n][k]
__device__ __nv_bfloat16 g_Wkh[512*512], g_Wkl[512*512];
__device__ __nv_bfloat16 g_Wvh[512*512], g_Wvl[512*512];

// ---------------------------------------------------------------------------
// Helpers: mma.sync / ldmatrix (plain sm_103-compatible PTX, no 'a' features)
// ---------------------------------------------------------------------------
__device__ __forceinline__ uint32_t smem_u32(const void* p) {
    uint32_t a;
    asm("{ .reg .u64 t; cvta.to.shared.u64 t, %1; cvt.u32.u64 %0, t; }" : "=r"(a) : "l"(p));
    return a;
}

__device__ __forceinline__ void mma_bf16(float* c, const uint32_t* a,
                                         uint32_t b0, uint32_t b1) {
    asm volatile(
        "mma.sync.aligned.m16n8k16.row.col.f32.bf16.bf16.f32 "
        "{%0,%1,%2,%3}, {%4,%5,%6,%7}, {%8,%9}, {%0,%1,%2,%3};"
        : "+f"(c[0]), "+f"(c[1]), "+f"(c[2]), "+f"(c[3])
        : "r"(a[0]), "r"(a[1]), "r"(a[2]), "r"(a[3]), "r"(b0), "r"(b1));
}

__device__ __forceinline__ void ldsm4(uint32_t* r, uint32_t a) {
    asm volatile("ldmatrix.sync.aligned.m8n8.x4.shared.b16 {%0,%1,%2,%3}, [%4];"
                 : "=r"(r[0]), "=r"(r[1]), "=r"(r[2]), "=r"(r[3]) : "r"(a));
}
__device__ __forceinline__ void ldsm4t(uint32_t* r, uint32_t a) {
    asm volatile("ldmatrix.sync.aligned.m8n8.x4.trans.shared.b16 {%0,%1,%2,%3}, [%4];"
                 : "=r"(r[0]), "=r"(r[1]), "=r"(r[2]), "=r"(r[3]) : "r"(a));
}

// pack two fp32 -> bf16x2 (lo in lower half)
__device__ __forceinline__ uint32_t packbf(float lo, float hi) {
    uint32_t d;
    asm("cvt.rn.bf16x2.f32 %0, %1, %2;" : "=r"(d) : "f"(hi), "f"(lo));
    return d;
}

#define SWZ(x) ((x) ^ (((x) >> 3) & 0x70))

__device__ __forceinline__ void split2(float x, __nv_bfloat16& h, __nv_bfloat16& l) {
    h = __float2bfloat16_rn(x);
    l = __float2bfloat16_rn(x - __bfloat162float(h));
}

// Load 128 rows x 64 bf16 (128B rows, SW128-swizzled) into smem; 256 threads.
// Source rows have stride 512 bf16.
__device__ __forceinline__ void ld_tile(char* dst, const __nv_bfloat16* g, int t) {
#pragma unroll
    for (int it = 0; it < 4; it++) {
        int idx = it * 256 + t;
        int r = idx >> 3, sg = idx & 7;
        uint4 v = *((const uint4*)(g + (size_t)r * 512) + sg);
        *(uint4*)(dst + SWZ(r * 128 + sg * 16)) = v;
    }
}

// ---------------------------------------------------------------------------
// fp32 -> bf16 hi/lo split (elementwise)
// ---------------------------------------------------------------------------
__global__ void split_k(const float* __restrict__ src, __nv_bfloat16* __restrict__ hi,
                        __nv_bfloat16* __restrict__ lo, int n) {
    int i = blockIdx.x * blockDim.x + threadIdx.x;
    if (i < n) {
        __nv_bfloat16 h, l;
        split2(src[i], h, l);
        hi[i] = h; lo[i] = l;
    }
}

// W [512,512] -> W^T split bf16 [n][k]
__global__ void wsplit_t(const float* __restrict__ W, __nv_bfloat16* __restrict__ Wth,
                         __nv_bfloat16* __restrict__ Wtl) {
    __shared__ float tile[64][65];
    int t = threadIdx.x;
    int k0 = blockIdx.x * 64, n0 = blockIdx.y * 64;
#pragma unroll
    for (int it = 0; it < 16; it++) {
        int idx = it * 256 + t, r = idx >> 6, c = idx & 63;
        tile[r][c] = W[(size_t)(k0 + r) * 512 + n0 + c];
    }
    __syncthreads();
#pragma unroll
    for (int it = 0; it < 16; it++) {
        int idx = it * 256 + t, d = idx >> 6, mm = idx & 63;
        __nv_bfloat16 h, l;
        split2(tile[mm][d], h, l);
        size_t o = (size_t)(n0 + d) * 512 + k0 + mm;
        Wth[o] = h; Wtl[o] = l;
    }
}

// ---------------------------------------------------------------------------
// Projection GEMM: C[8192,512] = A @ W via mma.sync split-bf16.
// A hi/lo [m][k]; B = W^T hi/lo [n][k]. Output written split bf16.
// 256 thr = 8 warps; 128x128 tile; warp w -> rows w*16..w*16+15.
// ---------------------------------------------------------------------------
#define PAH 0
#define PAL 16384
#define PBH 32768
#define PBL 49152
#define P_SMEM 65536

__global__ __launch_bounds__(256) void proj_mma(
    const __nv_bfloat16* __restrict__ Ah, const __nv_bfloat16* __restrict__ Al,
    const __nv_bfloat16* __restrict__ Bh, const __nv_bfloat16* __restrict__ Bl,
    __nv_bfloat16* __restrict__ Ch, __nv_bfloat16* __restrict__ Cl) {
    extern __shared__ char sm[];
    const uint32_t sb = smem_u32(sm);
    const int t = threadIdx.x, w = t >> 5, l = t & 31;
    const int n0 = blockIdx.x * 128, m0 = blockIdx.y * 128;

    float C[64];
#pragma unroll
    for (int i = 0; i < 64; i++) C[i] = 0.f;

    for (int kc = 0; kc < 8; kc++) {
        __syncthreads();
        ld_tile(sm + PAH, Ah + (size_t)m0 * 512 + kc * 64, t);
        ld_tile(sm + PAL, Al + (size_t)m0 * 512 + kc * 64, t);
        ld_tile(sm + PBH, Bh + (size_t)n0 * 512 + kc * 64, t);
        ld_tile(sm + PBL, Bl + (size_t)n0 * 512 + kc * 64, t);
        __syncthreads();

        uint32_t aH[4][4], aL[4][4];
#pragma unroll
        for (int ks = 0; ks < 4; ks++) {
            uint32_t off = (w * 16 + (l & 15)) * 128 + ks * 32 + (l >> 4) * 16;
            ldsm4(aH[ks], sb + PAH + SWZ(off));
            ldsm4(aL[ks], sb + PAL + SWZ(off));
        }
#pragma unroll
        for (int tt = 0; tt < 16; tt++) {
            uint32_t bh[8], bl[8];
            uint32_t base = (tt * 8 + (l & 7)) * 128 + (l >> 3) * 16;
            ldsm4(bh + 0, sb + PBH + SWZ(base));
            ldsm4(bh + 4, sb + PBH + SWZ(base + 64));
            ldsm4(bl + 0, sb + PBL + SWZ(base));
            ldsm4(bl + 4, sb + PBL + SWZ(base + 64));
            float* Ct = C + 4 * tt;
#pragma unroll
            for (int ks = 0; ks < 4; ks++) mma_bf16(Ct, aH[ks], bh[2*ks], bh[2*ks+1]);
#pragma unroll
            for (int ks = 0; ks < 4; ks++) mma_bf16(Ct, aH[ks], bl[2*ks], bl[2*ks+1]);
#pragma unroll
            for (int ks = 0; ks < 4; ks++) mma_bf16(Ct, aL[ks], bh[2*ks], bh[2*ks+1]);
        }
    }

    const int row = m0 + w * 16 + (l >> 2);
    const int cb = 2 * (l & 3);
#pragma unroll
    for (int tt = 0; tt < 16; tt++) {
        int col = n0 + tt * 8 + cb;
        float e0 = C[4*tt], e1 = C[4*tt+1], e2 = C[4*tt+2], e3 = C[4*tt+3];
        float h0 = __bfloat162float(__float2bfloat16_rn(e0));
        float h1 = __bfloat162float(__float2bfloat16_rn(e1));
        float h2 = __bfloat162float(__float2bfloat16_rn(e2));
        float h3 = __bfloat162float(__float2bfloat16_rn(e3));
        *(uint32_t*)&Ch[(size_t)row * 512 + col]       = packbf(h0, h1);
        *(uint32_t*)&Cl[(size_t)row * 512 + col]       = packbf(e0 - h0, e1 - h1);
        *(uint32_t*)&Ch[(size_t)(row + 8) * 512 + col] = packbf(h2, h3);
        *(uint32_t*)&Cl[(size_t)(row + 8) * 512 + col] = packbf(e2 - h2, e3 - h3);
    }
}

// ---------------------------------------------------------------------------
// Attention: FA2-style, per (b, h, 128-q tile). 256 thr = 8 warps.
// Warp w owns q rows w*16..+15. Q frags register-resident; ctx accumulated
// with online-softmax rescaling; raw logits streamed to align; in-kernel
// epilogue normalizes align from L2.
// ---------------------------------------------------------------------------
#define AQH 0
#define AQL 16384
#define AKH 32768
#define AKL 49152
#define AVH 65536
#define AVL 81920
#define ARM 98304
#define ARI 98816
#define A_SMEM 99328

__global__ __launch_bounds__(256) void attn_mma(
    const int* __restrict__ mem_len, const int* __restrict__ qry_len,
    float* __restrict__ ctx_out, float* __restrict__ align_out) {
    extern __shared__ char sm[];
    const uint32_t sb = smem_u32(sm);
    const int t = threadIdx.x, w = t >> 5, l = t & 31;
    const int q0 = blockIdx.x * 128, h = blockIdx.y, b = blockIdx.z;
    const int mlen = mem_len[b], qlen = qry_len[b];
    float* arow = align_out + (size_t)(b * 8 + h) * 1024 * 1024;

    const int r0 = l >> 2;
    const int q_r0 = q0 + w * 16 + r0;
    const int q_r1 = q_r0 + 8;
    const int cb = 2 * (l & 3);

    // Q tile -> smem -> register fragments (loop-invariant)
    ld_tile(sm + AQH, g_Qhi + (size_t)(b * 1024 + q0) * 512 + h * 64, t);
    ld_tile(sm + AQL, g_Qlo + (size_t)(b * 1024 + q0) * 512 + h * 64, t);
    __syncthreads();
    uint32_t aQh[4][4], aQl[4][4];
#pragma unroll
    for (int ks = 0; ks < 4; ks++) {
        uint32_t off = (w * 16 + (l & 15)) * 128 + ks * 32 + (l >> 4) * 16;
        ldsm4(aQh[ks], sb + AQH + SWZ(off));
        ldsm4(aQl[ks], sb + AQL + SWZ(off));
    }

    float ctx[32];
#pragma unroll
    for (int i = 0; i < 32; i++) ctx[i] = 0.f;
    float m0 = -INFINITY, m1 = -INFINITY, l0 = 0.f, l1 = 0.f;
    const bool qv0 = q_r0 < qlen, qv1 = q_r1 < qlen;

    for (int kt = 0; kt < 8; kt++) {
        const int k0 = kt * 128;
        __syncthreads();
        ld_tile(sm + AKH, g_Khi + (size_t)(b * 1024 + k0) * 512 + h * 64, t);
        ld_tile(sm + AKL, g_Klo + (size_t)(b * 1024 + k0) * 512 + h * 64, t);
        ld_tile(sm + AVH, g_Vhi + (size_t)(b * 1024 + k0) * 512 + h * 64, t);
        ld_tile(sm + AVL, g_Vlo + (size_t)(b * 1024 + k0) * 512 + h * 64, t);
        __syncthreads();

        // ---- S = (Qh+Ql)(Kh+Kl)^T, split 3-pass ----
        float S[64];
#pragma unroll
        for (int i = 0; i < 64; i++) S[i] = 0.f;
#pragma unroll
        for (int tt = 0; tt < 16; tt++) {
            uint32_t bh[8], bl[8];
            uint32_t base = (tt * 8 + (l & 7)) * 128 + (l >> 3) * 16;
            ldsm4(bh + 0, sb + AKH + SWZ(base));
            ldsm4(bh + 4, sb + AKH + SWZ(base + 64));
            ldsm4(bl + 0, sb + AKL + SWZ(base));
            ldsm4(bl + 4, sb + AKL + SWZ(base + 64));
            float* St = S + 4 * tt;
#pragma unroll
            for (int ks = 0; ks < 4; ks++) mma_bf16(St, aQh[ks], bh[2*ks], bh[2*ks+1]);
#pragma unroll
            for (int ks = 0; ks < 4; ks++) mma_bf16(St, aQh[ks], bl[2*ks], bl[2*ks+1]);
#pragma unroll
            for (int ks = 0; ks < 4; ks++) mma_bf16(St, aQl[ks], bh[2*ks], bh[2*ks+1]);
        }

        // ---- mask + scale + stream raw logits + tile max ----
        float tm0 = -INFINITY, tm1 = -INFINITY;
#pragma unroll
        for (int tt = 0; tt < 16; tt++) {
            const int mk = k0 + tt * 8 + cb;
#pragma unroll
            for (int e = 0; e < 2; e++) {
                const int m_ = mk + e;
                bool ok0 = qv0 && (m_ <= q_r0) && (m_ < mlen);
                bool ok1 = qv1 && (m_ <= q_r1) && (m_ < mlen);
                S[4*tt + e]     = ok0 ? S[4*tt + e]     * 0.125f : NEG_INF_F;
                S[4*tt + 2 + e] = ok1 ? S[4*tt + 2 + e] * 0.125f : NEG_INF_F;
            }
            *(float2*)(arow + (size_t)q_r0 * 1024 + mk) = make_float2(S[4*tt], S[4*tt+1]);
            *(float2*)(arow + (size_t)q_r1 * 1024 + mk) = make_float2(S[4*tt+2], S[4*tt+3]);
            tm0 = fmaxf(tm0, fmaxf(S[4*tt], S[4*tt+1]));
            tm1 = fmaxf(tm1, fmaxf(S[4*tt+2], S[4*tt+3]));
        }
        tm0 = fmaxf(tm0, __shfl_xor_sync(0xffffffffu, tm0, 1));
        tm0 = fmaxf(tm0, __shfl_xor_sync(0xffffffffu, tm0, 2));
        tm1 = fmaxf(tm1, __shfl_xor_sync(0xffffffffu, tm1, 1));
        tm1 = fmaxf(tm1, __shfl_xor_sync(0xffffffffu, tm1, 2));

        const float nm0 = fmaxf(m0, tm0), nm1 = fmaxf(m1, tm1);
        const float f0 = __expf(m0 - nm0), f1 = __expf(m1 - nm1);
        m0 = nm0; m1 = nm1;
#pragma unroll
        for (int td = 0; td < 8; td++) {
            ctx[4*td]   *= f0; ctx[4*td+1] *= f0;
            ctx[4*td+2] *= f1; ctx[4*td+3] *= f1;
        }
        float s0 = 0.f, s1 = 0.f;
#pragma unroll
        for (int i = 0; i < 64; i += 4) {
            S[i]   = __expf(S[i]   - nm0); S[i+1] = __expf(S[i+1] - nm0);
            S[i+2] = __expf(S[i+2] - nm1); S[i+3] = __expf(S[i+3] - nm1);
            s0 += S[i] + S[i+1];
            s1 += S[i+2] + S[i+3];
        }
        l0 = l0 * f0 + s0;
        l1 = l1 * f1 + s1;

        // ---- PV: ctx += P @ V  (P from S C-frags reused as A-frags) ----
#pragma unroll
        for (int kk = 0; kk < 8; kk++) {
            uint32_t aH[4], aL[4];
#pragma unroll
            for (int j = 0; j < 4; j++) {
                float e0 = S[8*kk + 2*j], e1 = S[8*kk + 2*j + 1];
                float h0 = __bfloat162float(__float2bfloat16_rn(e0));
                float h1 = __bfloat162float(__float2bfloat16_rn(e1));
                aH[j] = packbf(h0, h1);
                aL[j] = packbf(e0 - h0, e1 - h1);
            }
#pragma unroll
            for (int tdp = 0; tdp < 4; tdp++) {
                uint32_t vh[4], vl[4];
                uint32_t base = (kk * 16 + (l & 15)) * 128 + tdp * 32 + (l >> 4) * 16;
                ldsm4t(vh, sb + AVH + SWZ(base));
                ldsm4t(vl, sb + AVL + SWZ(base));
                float* c0 = ctx + 4 * (2 * tdp);
                float* c1 = ctx + 4 * (2 * tdp + 1);
                mma_bf16(c0, aH, vh[0], vh[1]); mma_bf16(c1, aH, vh[2], vh[3]);
                mma_bf16(c0, aH, vl[0], vl[1]); mma_bf16(c1, aH, vl[2], vl[3]);
                mma_bf16(c0, aL, vh[0], vh[1]); mma_bf16(c1, aL, vh[2], vh[3]);
            }
        }
    }

    // ---- finalize: reduce l, write ctx ----
    l0 += __shfl_xor_sync(0xffffffffu, l0, 1);
    l0 += __shfl_xor_sync(0xffffffffu, l0, 2);
    l1 += __shfl_xor_sync(0xffffffffu, l1, 1);
    l1 += __shfl_xor_sync(0xffffffffu, l1, 2);
    const float i0 = 1.0f / l0, i1 = 1.0f / l1;
#pragma unroll
    for (int td = 0; td < 8; td++) {
        *(float2*)(ctx_out + (size_t)(b * 1024 + q_r0) * 512 + h * 64 + td * 8 + cb) =
            make_float2(ctx[4*td] * i0, ctx[4*td+1] * i0);
        *(float2*)(ctx_out + (size_t)(b * 1024 + q_r1) * 512 + h * 64 + td * 8 + cb) =
            make_float2(ctx[4*td+2] * i1, ctx[4*td+3] * i1);
    }

    // ---- epilogue: normalize align rows (L2-hot) ----
    if ((l & 3) == 0) {
        ((float*)(sm + ARM))[w * 16 + r0]     = m0;
        ((float*)(sm + ARM))[w * 16 + r0 + 8] = m1;
        ((float*)(sm + ARI))[w * 16 + r0]     = i0;
        ((float*)(sm + ARI))[w * 16 + r0 + 8] = i1;
    }
    __syncthreads();
    const float* RM = (const float*)(sm + ARM);
    const float* RI = (const float*)(sm + ARI);
#pragma unroll 4
    for (int it = 0; it < 128; it++) {
        int idx = it * 256 + t;
        int row = idx >> 8, c4 = idx & 255;
        float* p = arow + (size_t)(q0 + row) * 1024 + c4 * 4;
        const float mm = RM[row], iv = RI[row];
        float4 v = *(float4*)p;
        v.x = __expf(v.x - mm) * iv;
        v.y = __expf(v.y - mm) * iv;
        v.z = __expf(v.z - mm) * iv;
        v.w = __expf(v.w - mm) * iv;
        *(float4*)p = v;
    }
}

// ---------------------------------------------------------------------------
extern "C" void kernel_launch(void* const* d_in, const int* in_sizes, int n_in,
                              void* d_out, int out_size) {
    const float* inputs = (const float*)d_in[0];
    const float* memory = (const float*)d_in[1];
    const float* Wq     = (const float*)d_in[2];
    const float* Wk     = (const float*)d_in[3];
    const float* Wv     = (const float*)d_in[4];
    const int*   mlen   = (const int*)d_in[5];
    const int*   qlen   = (const int*)d_in[6];

    float* out   = (float*)d_out;
    float* ctx   = out;
    float* align = out + (size_t)8 * 1024 * 512;

    __nv_bfloat16 *Ihi, *Ilo, *Mhi, *Mlo, *Qhi, *Qlo, *Khi, *Klo, *Vhi, *Vlo;
    __nv_bfloat16 *Wqh, *Wql, *Wkh, *Wkl, *Wvh, *Wvl;
    cudaGetSymbolAddress((void**)&Ihi, g_Ihi); cudaGetSymbolAddress((void**)&Ilo, g_Ilo);
    cudaGetSymbolAddress((void**)&Mhi, g_Mhi); cudaGetSymbolAddress((void**)&Mlo, g_Mlo);
    cudaGetSymbolAddress((void**)&Qhi, g_Qhi); cudaGetSymbolAddress((void**)&Qlo, g_Qlo);
    cudaGetSymbolAddress((void**)&Khi, g_Khi); cudaGetSymbolAddress((void**)&Klo, g_Klo);
    cudaGetSymbolAddress((void**)&Vhi, g_Vhi); cudaGetSymbolAddress((void**)&Vlo, g_Vlo);
    cudaGetSymbolAddress((void**)&Wqh, g_Wqh); cudaGetSymbolAddress((void**)&Wql, g_Wql);
    cudaGetSymbolAddress((void**)&Wkh, g_Wkh); cudaGetSymbolAddress((void**)&Wkl, g_Wkl);
    cudaGetSymbolAddress((void**)&Wvh, g_Wvh); cudaGetSymbolAddress((void**)&Wvl, g_Wvl);

    cudaFuncSetAttribute(proj_mma, cudaFuncAttributeMaxDynamicSharedMemorySize, P_SMEM);
    cudaFuncSetAttribute(attn_mma, cudaFuncAttributeMaxDynamicSharedMemorySize, A_SMEM);

    split_k<<<NELEM / 256, 256>>>(inputs, Ihi, Ilo, NELEM);
    split_k<<<NELEM / 256, 256>>>(memory, Mhi, Mlo, NELEM);
    wsplit_t<<<dim3(8, 8), 256>>>(Wq, Wqh, Wql);
    wsplit_t<<<dim3(8, 8), 256>>>(Wk, Wkh, Wkl);
    wsplit_t<<<dim3(8, 8), 256>>>(Wv, Wvh, Wvl);

    dim3 pgrid(4, 64);
    proj_mma<<<pgrid, 256, P_SMEM>>>(Ihi, Ilo, Wqh, Wql, Qhi, Qlo);
    proj_mma<<<pgrid, 256, P_SMEM>>>(Mhi, Mlo, Wkh, Wkl, Khi, Klo);
    proj_mma<<<pgrid, 256, P_SMEM>>>(Mhi, Mlo, Wvh, Wvl, Vhi, Vlo);

    attn_mma<<<dim3(8, 8, 8), 256, A_SMEM>>>(mlen, qlen, ctx, align);
}

// round 10
// speedup vs baseline: 2.5999x; 1.0467x over previous
#include <cuda_runtime.h>
#include <cuda_bf16.h>
#include <math.h>
#include <stdint.h>

#define NEG_INF_F (-4294967295.0f)
#define NELEM (8 * 1024 * 512)

// ---------------------------------------------------------------------------
// Static device scratch (bf16 hi/lo split arrays)
// ---------------------------------------------------------------------------
__device__ __nv_bfloat16 g_Ihi[NELEM], g_Ilo[NELEM];
__device__ __nv_bfloat16 g_Mhi[NELEM], g_Mlo[NELEM];
__device__ __nv_bfloat16 g_Qhi[NELEM], g_Qlo[NELEM];
__device__ __nv_bfloat16 g_Khi[NELEM], g_Klo[NELEM];
__device__ __nv_bfloat16 g_Vhi[NELEM], g_Vlo[NELEM];
__device__ __nv_bfloat16 g_Wqh[512*512], g_Wql[512*512];
__device__ __nv_bfloat16 g_Wkh[512*512], g_Wkl[512*512];
__device__ __nv_bfloat16 g_Wvh[512*512], g_Wvl[512*512];

// ---------------------------------------------------------------------------
// PTX helpers (plain sm_103-target-compatible: mma.sync/ldmatrix/cp.async)
// ---------------------------------------------------------------------------
__device__ __forceinline__ uint32_t smem_u32(const void* p) {
    uint32_t a;
    asm("{ .reg .u64 t; cvta.to.shared.u64 t, %1; cvt.u32.u64 %0, t; }" : "=r"(a) : "l"(p));
    return a;
}
__device__ __forceinline__ void mma_bf16(float* c, const uint32_t* a,
                                         uint32_t b0, uint32_t b1) {
    asm volatile(
        "mma.sync.aligned.m16n8k16.row.col.f32.bf16.bf16.f32 "
        "{%0,%1,%2,%3}, {%4,%5,%6,%7}, {%8,%9}, {%0,%1,%2,%3};"
        : "+f"(c[0]), "+f"(c[1]), "+f"(c[2]), "+f"(c[3])
        : "r"(a[0]), "r"(a[1]), "r"(a[2]), "r"(a[3]), "r"(b0), "r"(b1));
}
__device__ __forceinline__ void ldsm4(uint32_t* r, uint32_t a) {
    asm volatile("ldmatrix.sync.aligned.m8n8.x4.shared.b16 {%0,%1,%2,%3}, [%4];"
                 : "=r"(r[0]), "=r"(r[1]), "=r"(r[2]), "=r"(r[3]) : "r"(a));
}
__device__ __forceinline__ void ldsm4t(uint32_t* r, uint32_t a) {
    asm volatile("ldmatrix.sync.aligned.m8n8.x4.trans.shared.b16 {%0,%1,%2,%3}, [%4];"
                 : "=r"(r[0]), "=r"(r[1]), "=r"(r[2]), "=r"(r[3]) : "r"(a));
}
__device__ __forceinline__ uint32_t packbf(float lo, float hi) {
    uint32_t d;
    asm("cvt.rn.bf16x2.f32 %0, %1, %2;" : "=r"(d) : "f"(hi), "f"(lo));
    return d;
}
__device__ __forceinline__ void cpa16(uint32_t s, const void* g) {
    asm volatile("cp.async.cg.shared.global [%0], [%1], 16;" :: "r"(s), "l"(g));
}
#define CPA_COMMIT() asm volatile("cp.async.commit_group;" ::: "memory")
#define CPA_WAIT(n)  asm volatile("cp.async.wait_group %0;" :: "n"(n) : "memory")

#define SWZ(x) ((x) ^ (((x) >> 3) & 0x70))

__device__ __forceinline__ void split2(float x, __nv_bfloat16& h, __nv_bfloat16& l) {
    h = __float2bfloat16_rn(x);
    l = __float2bfloat16_rn(x - __bfloat162float(h));
}

// async load of one 128x64-bf16 tile (128B rows, SW128) ; 256 threads, 16B each
__device__ __forceinline__ void ld_tile_async(uint32_t dst, const __nv_bfloat16* g, int t) {
#pragma unroll
    for (int it = 0; it < 4; it++) {
        int idx = it * 256 + t;
        int r = idx >> 3, sg = idx & 7;
        cpa16(dst + SWZ(r * 128 + sg * 16), g + (size_t)r * 512 + sg * 8);
    }
}
// sync version (used for Q)
__device__ __forceinline__ void ld_tile(char* dst, const __nv_bfloat16* g, int t) {
#pragma unroll
    for (int it = 0; it < 4; it++) {
        int idx = it * 256 + t;
        int r = idx >> 3, sg = idx & 7;
        uint4 v = *((const uint4*)(g + (size_t)r * 512) + sg);
        *(uint4*)(dst + SWZ(r * 128 + sg * 16)) = v;
    }
}

// ---------------------------------------------------------------------------
// prep kernels
// ---------------------------------------------------------------------------
__global__ void split_k(const float* __restrict__ src, __nv_bfloat16* __restrict__ hi,
                        __nv_bfloat16* __restrict__ lo, int n) {
    int i = blockIdx.x * blockDim.x + threadIdx.x;
    if (i < n) {
        __nv_bfloat16 h, l;
        split2(src[i], h, l);
        hi[i] = h; lo[i] = l;
    }
}

__global__ void wsplit_t(const float* __restrict__ W, __nv_bfloat16* __restrict__ Wth,
                         __nv_bfloat16* __restrict__ Wtl) {
    __shared__ float tile[64][65];
    int t = threadIdx.x;
    int k0 = blockIdx.x * 64, n0 = blockIdx.y * 64;
#pragma unroll
    for (int it = 0; it < 16; it++) {
        int idx = it * 256 + t, r = idx >> 6, c = idx & 63;
        tile[r][c] = W[(size_t)(k0 + r) * 512 + n0 + c];
    }
    __syncthreads();
#pragma unroll
    for (int it = 0; it < 16; it++) {
        int idx = it * 256 + t, d = idx >> 6, mm = idx & 63;
        __nv_bfloat16 h, l;
        split2(tile[mm][d], h, l);
        size_t o = (size_t)(n0 + d) * 512 + k0 + mm;
        Wth[o] = h; Wtl[o] = l;
    }
}

// ---------------------------------------------------------------------------
// Projection GEMM with cp.async double buffering.
// stage s at offset s*65536: AH+0, AL+16384, BH+32768, BL+49152
// ---------------------------------------------------------------------------
#define P_SMEM 131072

__global__ __launch_bounds__(256) void proj_mma(
    const __nv_bfloat16* __restrict__ Ah, const __nv_bfloat16* __restrict__ Al,
    const __nv_bfloat16* __restrict__ Bh, const __nv_bfloat16* __restrict__ Bl,
    __nv_bfloat16* __restrict__ Ch, __nv_bfloat16* __restrict__ Cl) {
    extern __shared__ char sm[];
    const uint32_t sb = smem_u32(sm);
    const int t = threadIdx.x, w = t >> 5, l = t & 31;
    const int n0 = blockIdx.x * 128, m0 = blockIdx.y * 128;

    float C[64];
#pragma unroll
    for (int i = 0; i < 64; i++) C[i] = 0.f;

    // prologue: stage 0
    {
        uint32_t s0 = sb;
        ld_tile_async(s0 +     0, Ah + (size_t)m0 * 512, t);
        ld_tile_async(s0 + 16384, Al + (size_t)m0 * 512, t);
        ld_tile_async(s0 + 32768, Bh + (size_t)n0 * 512, t);
        ld_tile_async(s0 + 49152, Bl + (size_t)n0 * 512, t);
        CPA_COMMIT();
    }

    for (int kc = 0; kc < 8; kc++) {
        if (kc < 7) {
            uint32_t sn = sb + ((kc + 1) & 1) * 65536;
            ld_tile_async(sn +     0, Ah + (size_t)m0 * 512 + (kc + 1) * 64, t);
            ld_tile_async(sn + 16384, Al + (size_t)m0 * 512 + (kc + 1) * 64, t);
            ld_tile_async(sn + 32768, Bh + (size_t)n0 * 512 + (kc + 1) * 64, t);
            ld_tile_async(sn + 49152, Bl + (size_t)n0 * 512 + (kc + 1) * 64, t);
            CPA_COMMIT();
            CPA_WAIT(1);
        } else {
            CPA_WAIT(0);
        }
        __syncthreads();
        const uint32_t sc = sb + (kc & 1) * 65536;

        uint32_t aH[4][4], aL[4][4];
#pragma unroll
        for (int ks = 0; ks < 4; ks++) {
            uint32_t off = (w * 16 + (l & 15)) * 128 + ks * 32 + (l >> 4) * 16;
            ldsm4(aH[ks], sc + 0     + SWZ(off));
            ldsm4(aL[ks], sc + 16384 + SWZ(off));
        }
#pragma unroll
        for (int tt = 0; tt < 16; tt++) {
            uint32_t bh[8], bl[8];
            uint32_t base = (tt * 8 + (l & 7)) * 128 + (l >> 3) * 16;
            ldsm4(bh + 0, sc + 32768 + SWZ(base));
            ldsm4(bh + 4, sc + 32768 + SWZ(base + 64));
            ldsm4(bl + 0, sc + 49152 + SWZ(base));
            ldsm4(bl + 4, sc + 49152 + SWZ(base + 64));
            float* Ct = C + 4 * tt;
#pragma unroll
            for (int ks = 0; ks < 4; ks++) mma_bf16(Ct, aH[ks], bh[2*ks], bh[2*ks+1]);
#pragma unroll
            for (int ks = 0; ks < 4; ks++) mma_bf16(Ct, aH[ks], bl[2*ks], bl[2*ks+1]);
#pragma unroll
            for (int ks = 0; ks < 4; ks++) mma_bf16(Ct, aL[ks], bh[2*ks], bh[2*ks+1]);
        }
        __syncthreads();
    }

    const int row = m0 + w * 16 + (l >> 2);
    const int cb = 2 * (l & 3);
#pragma unroll
    for (int tt = 0; tt < 16; tt++) {
        int col = n0 + tt * 8 + cb;
        float e0 = C[4*tt], e1 = C[4*tt+1], e2 = C[4*tt+2], e3 = C[4*tt+3];
        float h0 = __bfloat162float(__float2bfloat16_rn(e0));
        float h1 = __bfloat162float(__float2bfloat16_rn(e1));
        float h2 = __bfloat162float(__float2bfloat16_rn(e2));
        float h3 = __bfloat162float(__float2bfloat16_rn(e3));
        *(uint32_t*)&Ch[(size_t)row * 512 + col]       = packbf(h0, h1);
        *(uint32_t*)&Cl[(size_t)row * 512 + col]       = packbf(e0 - h0, e1 - h1);
        *(uint32_t*)&Ch[(size_t)(row + 8) * 512 + col] = packbf(h2, h3);
        *(uint32_t*)&Cl[(size_t)(row + 8) * 512 + col] = packbf(e2 - h2, e3 - h3);
    }
}

// ---------------------------------------------------------------------------
// Attention: FA2-style + cp.async double-buffered K/V + exp-free epilogue.
// smem: Q hi/lo 32KB | stage0 64KB | stage1 64KB | FK 4KB | RM 512B | RI 512B
// ---------------------------------------------------------------------------
#define AQH 0
#define AQL 16384
#define AST 32768            // stage s at AST + s*65536 ; KH+0 KL+16K VH+32K VL+48K
#define AFK 163840           // float FK[8][128]
#define ARM 167936
#define ARI 168448
#define A_SMEM 168960

__global__ __launch_bounds__(256) void attn_mma(
    const int* __restrict__ mem_len, const int* __restrict__ qry_len,
    float* __restrict__ ctx_out, float* __restrict__ align_out) {
    extern __shared__ char sm[];
    const uint32_t sb = smem_u32(sm);
    const int t = threadIdx.x, w = t >> 5, l = t & 31;
    const int q0 = blockIdx.x * 128, h = blockIdx.y, b = blockIdx.z;
    const int mlen = mem_len[b], qlen = qry_len[b];
    float* arow = align_out + (size_t)(b * 8 + h) * 1024 * 1024;

    const int r0 = l >> 2;
    const int q_r0 = q0 + w * 16 + r0;
    const int q_r1 = q_r0 + 8;
    const int cb = 2 * (l & 3);

    const __nv_bfloat16* Kh = g_Khi + (size_t)(b * 1024) * 512 + h * 64;
    const __nv_bfloat16* Kl = g_Klo + (size_t)(b * 1024) * 512 + h * 64;
    const __nv_bfloat16* Vh = g_Vhi + (size_t)(b * 1024) * 512 + h * 64;
    const __nv_bfloat16* Vl = g_Vlo + (size_t)(b * 1024) * 512 + h * 64;

    // prologue: async stage 0, sync Q load
    {
        uint32_t s0 = sb + AST;
        ld_tile_async(s0 +     0, Kh, t);
        ld_tile_async(s0 + 16384, Kl, t);
        ld_tile_async(s0 + 32768, Vh, t);
        ld_tile_async(s0 + 49152, Vl, t);
        CPA_COMMIT();
    }
    ld_tile(sm + AQH, g_Qhi + (size_t)(b * 1024 + q0) * 512 + h * 64, t);
    ld_tile(sm + AQL, g_Qlo + (size_t)(b * 1024 + q0) * 512 + h * 64, t);
    __syncthreads();
    uint32_t aQh[4][4], aQl[4][4];
#pragma unroll
    for (int ks = 0; ks < 4; ks++) {
        uint32_t off = (w * 16 + (l & 15)) * 128 + ks * 32 + (l >> 4) * 16;
        ldsm4(aQh[ks], sb + AQH + SWZ(off));
        ldsm4(aQl[ks], sb + AQL + SWZ(off));
    }

    float ctx[32];
#pragma unroll
    for (int i = 0; i < 32; i++) ctx[i] = 0.f;
    float m0 = -INFINITY, m1 = -INFINITY, l0 = 0.f, l1 = 0.f;
    const bool qv0 = q_r0 < qlen, qv1 = q_r1 < qlen;
    float* FK = (float*)(sm + AFK);

    for (int kt = 0; kt < 8; kt++) {
        const int k0 = kt * 128;
        if (kt < 7) {
            uint32_t sn = sb + AST + ((kt + 1) & 1) * 65536;
            ld_tile_async(sn +     0, Kh + (size_t)(k0 + 128) * 512, t);
            ld_tile_async(sn + 16384, Kl + (size_t)(k0 + 128) * 512, t);
            ld_tile_async(sn + 32768, Vh + (size_t)(k0 + 128) * 512, t);
            ld_tile_async(sn + 49152, Vl + (size_t)(k0 + 128) * 512, t);
            CPA_COMMIT();
            CPA_WAIT(1);
        } else {
            CPA_WAIT(0);
        }
        __syncthreads();
        const uint32_t sc = sb + AST + (kt & 1) * 65536;

        // ---- S = (Qh+Ql)(Kh+Kl)^T, split 3-pass ----
        float S[64];
#pragma unroll
        for (int i = 0; i < 64; i++) S[i] = 0.f;
#pragma unroll
        for (int tt = 0; tt < 16; tt++) {
            uint32_t bh[8], bl[8];
            uint32_t base = (tt * 8 + (l & 7)) * 128 + (l >> 3) * 16;
            ldsm4(bh + 0, sc + 0     + SWZ(base));
            ldsm4(bh + 4, sc + 0     + SWZ(base + 64));
            ldsm4(bl + 0, sc + 16384 + SWZ(base));
            ldsm4(bl + 4, sc + 16384 + SWZ(base + 64));
            float* St = S + 4 * tt;
#pragma unroll
            for (int ks = 0; ks < 4; ks++) mma_bf16(St, aQh[ks], bh[2*ks], bh[2*ks+1]);
#pragma unroll
            for (int ks = 0; ks < 4; ks++) mma_bf16(St, aQh[ks], bl[2*ks], bl[2*ks+1]);
#pragma unroll
            for (int ks = 0; ks < 4; ks++) mma_bf16(St, aQl[ks], bh[2*ks], bh[2*ks+1]);
        }

        // ---- mask + scale, tile max ----
        float tm0 = -INFINITY, tm1 = -INFINITY;
#pragma unroll
        for (int tt = 0; tt < 16; tt++) {
            const int mk = k0 + tt * 8 + cb;
#pragma unroll
            for (int e = 0; e < 2; e++) {
                const int m_ = mk + e;
                bool ok0 = qv0 && (m_ <= q_r0) && (m_ < mlen);
                bool ok1 = qv1 && (m_ <= q_r1) && (m_ < mlen);
                S[4*tt + e]     = ok0 ? S[4*tt + e]     * 0.125f : NEG_INF_F;
                S[4*tt + 2 + e] = ok1 ? S[4*tt + 2 + e] * 0.125f : NEG_INF_F;
            }
            tm0 = fmaxf(tm0, fmaxf(S[4*tt], S[4*tt+1]));
            tm1 = fmaxf(tm1, fmaxf(S[4*tt+2], S[4*tt+3]));
        }
        tm0 = fmaxf(tm0, __shfl_xor_sync(0xffffffffu, tm0, 1));
        tm0 = fmaxf(tm0, __shfl_xor_sync(0xffffffffu, tm0, 2));
        tm1 = fmaxf(tm1, __shfl_xor_sync(0xffffffffu, tm1, 1));
        tm1 = fmaxf(tm1, __shfl_xor_sync(0xffffffffu, tm1, 2));

        const float nm0 = fmaxf(m0, tm0), nm1 = fmaxf(m1, tm1);
        const float f0 = __expf(m0 - nm0), f1 = __expf(m1 - nm1);
        m0 = nm0; m1 = nm1;
        if ((l & 3) == 0) {                    // record running max for epilogue
            FK[kt * 128 + w * 16 + r0]     = nm0;
            FK[kt * 128 + w * 16 + r0 + 8] = nm1;
        }
#pragma unroll
        for (int td = 0; td < 8; td++) {
            ctx[4*td]   *= f0; ctx[4*td+1] *= f0;
            ctx[4*td+2] *= f1; ctx[4*td+3] *= f1;
        }
        float s0 = 0.f, s1 = 0.f;
#pragma unroll
        for (int i = 0; i < 64; i += 4) {
            S[i]   = __expf(S[i]   - nm0); S[i+1] = __expf(S[i+1] - nm0);
            S[i+2] = __expf(S[i+2] - nm1); S[i+3] = __expf(S[i+3] - nm1);
            s0 += S[i] + S[i+1];
            s1 += S[i+2] + S[i+3];
        }
        l0 = l0 * f0 + s0;
        l1 = l1 * f1 + s1;

        // ---- stream unnormalized P = exp(S - m_kt) to align buffer ----
#pragma unroll
        for (int tt = 0; tt < 16; tt++) {
            const int mk = k0 + tt * 8 + cb;
            *(float2*)(arow + (size_t)q_r0 * 1024 + mk) = make_float2(S[4*tt], S[4*tt+1]);
            *(float2*)(arow + (size_t)q_r1 * 1024 + mk) = make_float2(S[4*tt+2], S[4*tt+3]);
        }

        // ---- PV: ctx += P @ V ----
#pragma unroll
        for (int kk = 0; kk < 8; kk++) {
            uint32_t aH[4], aL[4];
#pragma unroll
            for (int j = 0; j < 4; j++) {
                float e0 = S[8*kk + 2*j], e1 = S[8*kk + 2*j + 1];
                float h0 = __bfloat162float(__float2bfloat16_rn(e0));
                float h1 = __bfloat162float(__float2bfloat16_rn(e1));
                aH[j] = packbf(h0, h1);
                aL[j] = packbf(e0 - h0, e1 - h1);
            }
#pragma unroll
            for (int tdp = 0; tdp < 4; tdp++) {
                uint32_t vh[4], vl[4];
                uint32_t base = (kk * 16 + (l & 15)) * 128 + tdp * 32 + (l >> 4) * 16;
                ldsm4t(vh, sc + 32768 + SWZ(base));
                ldsm4t(vl, sc + 49152 + SWZ(base));
                float* c0 = ctx + 4 * (2 * tdp);
                float* c1 = ctx + 4 * (2 * tdp + 1);
                mma_bf16(c0, aH, vh[0], vh[1]); mma_bf16(c1, aH, vh[2], vh[3]);
                mma_bf16(c0, aH, vl[0], vl[1]); mma_bf16(c1, aH, vl[2], vl[3]);
                mma_bf16(c0, aL, vh[0], vh[1]); mma_bf16(c1, aL, vh[2], vh[3]);
            }
        }
        __syncthreads();
    }

    // ---- finalize: reduce l, write ctx ----
    l0 += __shfl_xor_sync(0xffffffffu, l0, 1);
    l0 += __shfl_xor_sync(0xffffffffu, l0, 2);
    l1 += __shfl_xor_sync(0xffffffffu, l1, 1);
    l1 += __shfl_xor_sync(0xffffffffu, l1, 2);
    const float i0 = 1.0f / l0, i1 = 1.0f / l1;
#pragma unroll
    for (int td = 0; td < 8; td++) {
        *(float2*)(ctx_out + (size_t)(b * 1024 + q_r0) * 512 + h * 64 + td * 8 + cb) =
            make_float2(ctx[4*td] * i0, ctx[4*td+1] * i0);
        *(float2*)(ctx_out + (size_t)(b * 1024 + q_r1) * 512 + h * 64 + td * 8 + cb) =
            make_float2(ctx[4*td+2] * i1, ctx[4*td+3] * i1);
    }

    // ---- epilogue: factor table, then multiply-only normalize pass ----
    if ((l & 3) == 0) {
        ((float*)(sm + ARM))[w * 16 + r0]     = m0;
        ((float*)(sm + ARM))[w * 16 + r0 + 8] = m1;
        ((float*)(sm + ARI))[w * 16 + r0]     = i0;
        ((float*)(sm + ARI))[w * 16 + r0 + 8] = i1;
    }
    __syncthreads();
    {
        const float* RM = (const float*)(sm + ARM);
        const float* RI = (const float*)(sm + ARI);
#pragma unroll
        for (int i = 0; i < 4; i++) {
            int e = t * 4 + i;
            int ktt = e >> 7, row = e & 127;
            FK[ktt * 128 + row] = __expf(FK[ktt * 128 + row] - RM[row]) * RI[row];
        }
    }
    __syncthreads();
#pragma unroll 4
    for (int it = 0; it < 128; it++) {
        int idx = it * 256 + t;
        int row = idx >> 8, c4 = idx & 255;           // c4*4 = column
        float* p = arow + (size_t)(q0 + row) * 1024 + c4 * 4;
        const float f = FK[(c4 >> 5) * 128 + row];    // tile = col/128 = c4/32
        float4 v = *(float4*)p;
        v.x *= f; v.y *= f; v.z *= f; v.w *= f;
        *(float4*)p = v;
    }
}

// ---------------------------------------------------------------------------
extern "C" void kernel_launch(void* const* d_in, const int* in_sizes, int n_in,
                              void* d_out, int out_size) {
    const float* inputs = (const float*)d_in[0];
    const float* memory = (const float*)d_in[1];
    const float* Wq     = (const float*)d_in[2];
    const float* Wk     = (const float*)d_in[3];
    const float* Wv     = (const float*)d_in[4];
    const int*   mlen   = (const int*)d_in[5];
    const int*   qlen   = (const int*)d_in[6];

    float* out   = (float*)d_out;
    float* ctx   = out;
    float* align = out + (size_t)8 * 1024 * 512;

    __nv_bfloat16 *Ihi, *Ilo, *Mhi, *Mlo, *Qhi, *Qlo, *Khi, *Klo, *Vhi, *Vlo;
    __nv_bfloat16 *Wqh, *Wql, *Wkh, *Wkl, *Wvh, *Wvl;
    cudaGetSymbolAddress((void**)&Ihi, g_Ihi); cudaGetSymbolAddress((void**)&Ilo, g_Ilo);
    cudaGetSymbolAddress((void**)&Mhi, g_Mhi); cudaGetSymbolAddress((void**)&Mlo, g_Mlo);
    cudaGetSymbolAddress((void**)&Qhi, g_Qhi); cudaGetSymbolAddress((void**)&Qlo, g_Qlo);
    cudaGetSymbolAddress((void**)&Khi, g_Khi); cudaGetSymbolAddress((void**)&Klo, g_Klo);
    cudaGetSymbolAddress((void**)&Vhi, g_Vhi); cudaGetSymbolAddress((void**)&Vlo, g_Vlo);
    cudaGetSymbolAddress((void**)&Wqh, g_Wqh); cudaGetSymbolAddress((void**)&Wql, g_Wql);
    cudaGetSymbolAddress((void**)&Wkh, g_Wkh); cudaGetSymbolAddress((void**)&Wkl, g_Wkl);
    cudaGetSymbolAddress((void**)&Wvh, g_Wvh); cudaGetSymbolAddress((void**)&Wvl, g_Wvl);

    cudaFuncSetAttribute(proj_mma, cudaFuncAttributeMaxDynamicSharedMemorySize, P_SMEM);
    cudaFuncSetAttribute(attn_mma, cudaFuncAttributeMaxDynamicSharedMemorySize, A_SMEM);

    split_k<<<NELEM / 256, 256>>>(inputs, Ihi, Ilo, NELEM);
    split_k<<<NELEM / 256, 256>>>(memory, Mhi, Mlo, NELEM);
    wsplit_t<<<dim3(8, 8), 256>>>(Wq, Wqh, Wql);
    wsplit_t<<<dim3(8, 8), 256>>>(Wk, Wkh, Wkl);
    wsplit_t<<<dim3(8, 8), 256>>>(Wv, Wvh, Wvl);

    dim3 pgrid(4, 64);
    proj_mma<<<pgrid, 256, P_SMEM>>>(Ihi, Ilo, Wqh, Wql, Qhi, Qlo);
    proj_mma<<<pgrid, 256, P_SMEM>>>(Mhi, Mlo, Wkh, Wkl, Khi, Klo);
    proj_mma<<<pgrid, 256, P_SMEM>>>(Mhi, Mlo, Wvh, Wvl, Vhi, Vlo);

    attn_mma<<<dim3(8, 8, 8), 256, A_SMEM>>>(mlen, qlen, ctx, align);
}

// round 11
// speedup vs baseline: 3.4880x; 1.3416x over previous
#include <cuda_runtime.h>
#include <cuda_bf16.h>
#include <math.h>
#include <stdint.h>

#define NEG_INF_F (-4294967295.0f)
#define NELEM (8 * 1024 * 512)
#define INV1024 0.0009765625f

// ---------------------------------------------------------------------------
// Static device scratch (bf16 hi/lo split arrays)
// ---------------------------------------------------------------------------
__device__ __nv_bfloat16 g_Ihi[NELEM], g_Ilo[NELEM];
__device__ __nv_bfloat16 g_Mhi[NELEM], g_Mlo[NELEM];
__device__ __nv_bfloat16 g_Qhi[NELEM], g_Qlo[NELEM];
__device__ __nv_bfloat16 g_Khi[NELEM], g_Klo[NELEM];
__device__ __nv_bfloat16 g_Vhi[NELEM], g_Vlo[NELEM];
__device__ __nv_bfloat16 g_Wqh[512*512], g_Wql[512*512];
__device__ __nv_bfloat16 g_Wkh[512*512], g_Wkl[512*512];
__device__ __nv_bfloat16 g_Wvh[512*512], g_Wvl[512*512];
__device__ float g_Vmean[8 * 8 * 64];

// ---------------------------------------------------------------------------
// PTX helpers (plain sm_103-target-compatible: mma.sync/ldmatrix/cp.async)
// ---------------------------------------------------------------------------
__device__ __forceinline__ uint32_t smem_u32(const void* p) {
    uint32_t a;
    asm("{ .reg .u64 t; cvta.to.shared.u64 t, %1; cvt.u32.u64 %0, t; }" : "=r"(a) : "l"(p));
    return a;
}
__device__ __forceinline__ void mma_bf16(float* c, const uint32_t* a,
                                         uint32_t b0, uint32_t b1) {
    asm volatile(
        "mma.sync.aligned.m16n8k16.row.col.f32.bf16.bf16.f32 "
        "{%0,%1,%2,%3}, {%4,%5,%6,%7}, {%8,%9}, {%0,%1,%2,%3};"
        : "+f"(c[0]), "+f"(c[1]), "+f"(c[2]), "+f"(c[3])
        : "r"(a[0]), "r"(a[1]), "r"(a[2]), "r"(a[3]), "r"(b0), "r"(b1));
}
__device__ __forceinline__ void ldsm4(uint32_t* r, uint32_t a) {
    asm volatile("ldmatrix.sync.aligned.m8n8.x4.shared.b16 {%0,%1,%2,%3}, [%4];"
                 : "=r"(r[0]), "=r"(r[1]), "=r"(r[2]), "=r"(r[3]) : "r"(a));
}
__device__ __forceinline__ void ldsm4t(uint32_t* r, uint32_t a) {
    asm volatile("ldmatrix.sync.aligned.m8n8.x4.trans.shared.b16 {%0,%1,%2,%3}, [%4];"
                 : "=r"(r[0]), "=r"(r[1]), "=r"(r[2]), "=r"(r[3]) : "r"(a));
}
__device__ __forceinline__ uint32_t packbf(float lo, float hi) {
    uint32_t d;
    asm("cvt.rn.bf16x2.f32 %0, %1, %2;" : "=r"(d) : "f"(hi), "f"(lo));
    return d;
}
__device__ __forceinline__ void cpa16(uint32_t s, const void* g) {
    asm volatile("cp.async.cg.shared.global [%0], [%1], 16;" :: "r"(s), "l"(g));
}
#define CPA_COMMIT() asm volatile("cp.async.commit_group;" ::: "memory")
#define CPA_WAIT(n)  asm volatile("cp.async.wait_group %0;" :: "n"(n) : "memory")

#define SWZ(x) ((x) ^ (((x) >> 3) & 0x70))

__device__ __forceinline__ void split2(float x, __nv_bfloat16& h, __nv_bfloat16& l) {
    h = __float2bfloat16_rn(x);
    l = __float2bfloat16_rn(x - __bfloat162float(h));
}

__device__ __forceinline__ void ld_tile_async(uint32_t dst, const __nv_bfloat16* g, int t) {
#pragma unroll
    for (int it = 0; it < 4; it++) {
        int idx = it * 256 + t;
        int r = idx >> 3, sg = idx & 7;
        cpa16(dst + SWZ(r * 128 + sg * 16), g + (size_t)r * 512 + sg * 8);
    }
}
__device__ __forceinline__ void ld_tile(char* dst, const __nv_bfloat16* g, int t) {
#pragma unroll
    for (int it = 0; it < 4; it++) {
        int idx = it * 256 + t;
        int r = idx >> 3, sg = idx & 7;
        uint4 v = *((const uint4*)(g + (size_t)r * 512) + sg);
        *(uint4*)(dst + SWZ(r * 128 + sg * 16)) = v;
    }
}

// ---------------------------------------------------------------------------
// prep: fused hi/lo split of inputs+memory (vectorized), fused W^T splits
// ---------------------------------------------------------------------------
__global__ void split2_k(const float* __restrict__ in0, const float* __restrict__ in1) {
    const float* src = blockIdx.y ? in1 : in0;
    __nv_bfloat16* hi = blockIdx.y ? g_Mhi : g_Ihi;
    __nv_bfloat16* lo = blockIdx.y ? g_Mlo : g_Ilo;
    int i = (blockIdx.x * 256 + threadIdx.x) * 4;
    float4 v = *(const float4*)(src + i);
    float hx = __bfloat162float(__float2bfloat16_rn(v.x));
    float hy = __bfloat162float(__float2bfloat16_rn(v.y));
    float hz = __bfloat162float(__float2bfloat16_rn(v.z));
    float hw = __bfloat162float(__float2bfloat16_rn(v.w));
    *(uint2*)(hi + i) = make_uint2(packbf(hx, hy), packbf(hz, hw));
    *(uint2*)(lo + i) = make_uint2(packbf(v.x - hx, v.y - hy), packbf(v.z - hz, v.w - hw));
}

__global__ void wsplit_t(const float* __restrict__ W0, const float* __restrict__ W1,
                         const float* __restrict__ W2) {
    const float* W = blockIdx.z == 0 ? W0 : (blockIdx.z == 1 ? W1 : W2);
    __nv_bfloat16* Wth = blockIdx.z == 0 ? g_Wqh : (blockIdx.z == 1 ? g_Wkh : g_Wvh);
    __nv_bfloat16* Wtl = blockIdx.z == 0 ? g_Wql : (blockIdx.z == 1 ? g_Wkl : g_Wvl);
    __shared__ float tile[64][65];
    int t = threadIdx.x;
    int k0 = blockIdx.x * 64, n0 = blockIdx.y * 64;
#pragma unroll
    for (int it = 0; it < 16; it++) {
        int idx = it * 256 + t, r = idx >> 6, c = idx & 63;
        tile[r][c] = W[(size_t)(k0 + r) * 512 + n0 + c];
    }
    __syncthreads();
#pragma unroll
    for (int it = 0; it < 16; it++) {
        int idx = it * 256 + t, d = idx >> 6, mm = idx & 63;
        __nv_bfloat16 h, l;
        split2(tile[mm][d], h, l);
        size_t o = (size_t)(n0 + d) * 512 + k0 + mm;
        Wth[o] = h; Wtl[o] = l;
    }
}

// Vmean[b,h,d] = mean over all 1024 m of V  (for fully-masked query rows)
__global__ void vmean_k() {
    __shared__ float ps[4][64];
    int b = blockIdx.x >> 3, h = blockIdx.x & 7;
    int t = threadIdx.x, d = t & 63, part = t >> 6;
    float s = 0.f;
    for (int m = part * 256; m < part * 256 + 256; m++) {
        size_t gi = (size_t)(b * 1024 + m) * 512 + h * 64 + d;
        s += __bfloat162float(g_Vhi[gi]) + __bfloat162float(g_Vlo[gi]);
    }
    ps[part][d] = s;
    __syncthreads();
    if (part == 0)
        g_Vmean[(b * 8 + h) * 64 + d] =
            (ps[0][d] + ps[1][d] + ps[2][d] + ps[3][d]) * INV1024;
}

// ---------------------------------------------------------------------------
// Fused projection GEMMs (z selects Q/K/V), cp.async double buffered.
// ---------------------------------------------------------------------------
#define P_SMEM 131072

__global__ __launch_bounds__(256) void proj_mma() {
    const __nv_bfloat16 *Ah, *Al, *Bh, *Bl;
    __nv_bfloat16 *Ch, *Cl;
    if (blockIdx.z == 0)      { Ah = g_Ihi; Al = g_Ilo; Bh = g_Wqh; Bl = g_Wql; Ch = g_Qhi; Cl = g_Qlo; }
    else if (blockIdx.z == 1) { Ah = g_Mhi; Al = g_Mlo; Bh = g_Wkh; Bl = g_Wkl; Ch = g_Khi; Cl = g_Klo; }
    else                      { Ah = g_Mhi; Al = g_Mlo; Bh = g_Wvh; Bl = g_Wvl; Ch = g_Vhi; Cl = g_Vlo; }

    extern __shared__ char sm[];
    const uint32_t sb = smem_u32(sm);
    const int t = threadIdx.x, w = t >> 5, l = t & 31;
    const int n0 = blockIdx.x * 128, m0 = blockIdx.y * 128;

    float C[64];
#pragma unroll
    for (int i = 0; i < 64; i++) C[i] = 0.f;

    {
        uint32_t s0 = sb;
        ld_tile_async(s0 +     0, Ah + (size_t)m0 * 512, t);
        ld_tile_async(s0 + 16384, Al + (size_t)m0 * 512, t);
        ld_tile_async(s0 + 32768, Bh + (size_t)n0 * 512, t);
        ld_tile_async(s0 + 49152, Bl + (size_t)n0 * 512, t);
        CPA_COMMIT();
    }

    for (int kc = 0; kc < 8; kc++) {
        if (kc < 7) {
            uint32_t sn = sb + ((kc + 1) & 1) * 65536;
            ld_tile_async(sn +     0, Ah + (size_t)m0 * 512 + (kc + 1) * 64, t);
            ld_tile_async(sn + 16384, Al + (size_t)m0 * 512 + (kc + 1) * 64, t);
            ld_tile_async(sn + 32768, Bh + (size_t)n0 * 512 + (kc + 1) * 64, t);
            ld_tile_async(sn + 49152, Bl + (size_t)n0 * 512 + (kc + 1) * 64, t);
            CPA_COMMIT();
            CPA_WAIT(1);
        } else {
            CPA_WAIT(0);
        }
        __syncthreads();
        const uint32_t sc = sb + (kc & 1) * 65536;

        uint32_t aH[4][4], aL[4][4];
#pragma unroll
        for (int ks = 0; ks < 4; ks++) {
            uint32_t off = (w * 16 + (l & 15)) * 128 + ks * 32 + (l >> 4) * 16;
            ldsm4(aH[ks], sc + 0     + SWZ(off));
            ldsm4(aL[ks], sc + 16384 + SWZ(off));
        }
#pragma unroll
        for (int tt = 0; tt < 16; tt++) {
            uint32_t bh[8], bl[8];
            uint32_t base = (tt * 8 + (l & 7)) * 128 + (l >> 3) * 16;
            ldsm4(bh + 0, sc + 32768 + SWZ(base));
            ldsm4(bh + 4, sc + 32768 + SWZ(base + 64));
            ldsm4(bl + 0, sc + 49152 + SWZ(base));
            ldsm4(bl + 4, sc + 49152 + SWZ(base + 64));
            float* Ct = C + 4 * tt;
#pragma unroll
            for (int ks = 0; ks < 4; ks++) mma_bf16(Ct, aH[ks], bh[2*ks], bh[2*ks+1]);
#pragma unroll
            for (int ks = 0; ks < 4; ks++) mma_bf16(Ct, aH[ks], bl[2*ks], bl[2*ks+1]);
#pragma unroll
            for (int ks = 0; ks < 4; ks++) mma_bf16(Ct, aL[ks], bh[2*ks], bh[2*ks+1]);
        }
        __syncthreads();
    }

    const int row = m0 + w * 16 + (l >> 2);
    const int cb = 2 * (l & 3);
#pragma unroll
    for (int tt = 0; tt < 16; tt++) {
        int col = n0 + tt * 8 + cb;
        float e0 = C[4*tt], e1 = C[4*tt+1], e2 = C[4*tt+2], e3 = C[4*tt+3];
        float h0 = __bfloat162float(__float2bfloat16_rn(e0));
        float h1 = __bfloat162float(__float2bfloat16_rn(e1));
        float h2 = __bfloat162float(__float2bfloat16_rn(e2));
        float h3 = __bfloat162float(__float2bfloat16_rn(e3));
        *(uint32_t*)&Ch[(size_t)row * 512 + col]       = packbf(h0, h1);
        *(uint32_t*)&Cl[(size_t)row * 512 + col]       = packbf(e0 - h0, e1 - h1);
        *(uint32_t*)&Ch[(size_t)(row + 8) * 512 + col] = packbf(h2, h3);
        *(uint32_t*)&Cl[(size_t)(row + 8) * 512 + col] = packbf(e2 - h2, e3 - h3);
    }
}

// ---------------------------------------------------------------------------
// Attention: FA2-style, causal tile skipping (block i visits tiles 0..nvt-1).
// ---------------------------------------------------------------------------
#define AQH 0
#define AQL 16384
#define AST 32768            // stage s at AST + s*65536 ; KH+0 KL+16K VH+32K VL+48K
#define AFK 163840           // float FK[8][128]
#define ARM 167936
#define ARI 168448
#define A_SMEM 168960

__global__ __launch_bounds__(256) void attn_mma(
    const int* __restrict__ mem_len, const int* __restrict__ qry_len,
    float* __restrict__ ctx_out, float* __restrict__ align_out) {
    extern __shared__ char sm[];
    const uint32_t sb = smem_u32(sm);
    const int t = threadIdx.x, w = t >> 5, l = t & 31;
    const int qi = 7 - blockIdx.x;          // heavy blocks first
    const int q0 = qi * 128, h = blockIdx.y, b = blockIdx.z;
    const int mlen = mem_len[b], qlen = qry_len[b];
    const int nvt = min(qi + 1, (mlen + 127) >> 7);   // visited key tiles
    float* arow = align_out + (size_t)(b * 8 + h) * 1024 * 1024;

    const int r0 = l >> 2;
    const int q_r0 = q0 + w * 16 + r0;
    const int q_r1 = q_r0 + 8;
    const int cb = 2 * (l & 3);

    const __nv_bfloat16* Kh = g_Khi + (size_t)(b * 1024) * 512 + h * 64;
    const __nv_bfloat16* Kl = g_Klo + (size_t)(b * 1024) * 512 + h * 64;
    const __nv_bfloat16* Vh = g_Vhi + (size_t)(b * 1024) * 512 + h * 64;
    const __nv_bfloat16* Vl = g_Vlo + (size_t)(b * 1024) * 512 + h * 64;

    {
        uint32_t s0 = sb + AST;
        ld_tile_async(s0 +     0, Kh, t);
        ld_tile_async(s0 + 16384, Kl, t);
        ld_tile_async(s0 + 32768, Vh, t);
        ld_tile_async(s0 + 49152, Vl, t);
        CPA_COMMIT();
    }
    ld_tile(sm + AQH, g_Qhi + (size_t)(b * 1024 + q0) * 512 + h * 64, t);
    ld_tile(sm + AQL, g_Qlo + (size_t)(b * 1024 + q0) * 512 + h * 64, t);
    __syncthreads();
    uint32_t aQh[4][4], aQl[4][4];
#pragma unroll
    for (int ks = 0; ks < 4; ks++) {
        uint32_t off = (w * 16 + (l & 15)) * 128 + ks * 32 + (l >> 4) * 16;
        ldsm4(aQh[ks], sb + AQH + SWZ(off));
        ldsm4(aQl[ks], sb + AQL + SWZ(off));
    }

    float ctx[32];
#pragma unroll
    for (int i = 0; i < 32; i++) ctx[i] = 0.f;
    float m0 = -INFINITY, m1 = -INFINITY, l0 = 0.f, l1 = 0.f;
    const bool qv0 = q_r0 < qlen, qv1 = q_r1 < qlen;
    float* FK = (float*)(sm + AFK);

    for (int kt = 0; kt < nvt; kt++) {
        const int k0 = kt * 128;
        if (kt + 1 < nvt) {
            uint32_t sn = sb + AST + ((kt + 1) & 1) * 65536;
            ld_tile_async(sn +     0, Kh + (size_t)(k0 + 128) * 512, t);
            ld_tile_async(sn + 16384, Kl + (size_t)(k0 + 128) * 512, t);
            ld_tile_async(sn + 32768, Vh + (size_t)(k0 + 128) * 512, t);
            ld_tile_async(sn + 49152, Vl + (size_t)(k0 + 128) * 512, t);
            CPA_COMMIT();
            CPA_WAIT(1);
        } else {
            CPA_WAIT(0);
        }
        __syncthreads();
        const uint32_t sc = sb + AST + (kt & 1) * 65536;

        // ---- S = (Qh+Ql)(Kh+Kl)^T, split 3-pass ----
        float S[64];
#pragma unroll
        for (int i = 0; i < 64; i++) S[i] = 0.f;
#pragma unroll
        for (int tt = 0; tt < 16; tt++) {
            uint32_t bh[8], bl[8];
            uint32_t base = (tt * 8 + (l & 7)) * 128 + (l >> 3) * 16;
            ldsm4(bh + 0, sc + 0     + SWZ(base));
            ldsm4(bh + 4, sc + 0     + SWZ(base + 64));
            ldsm4(bl + 0, sc + 16384 + SWZ(base));
            ldsm4(bl + 4, sc + 16384 + SWZ(base + 64));
            float* St = S + 4 * tt;
#pragma unroll
            for (int ks = 0; ks < 4; ks++) mma_bf16(St, aQh[ks], bh[2*ks], bh[2*ks+1]);
#pragma unroll
            for (int ks = 0; ks < 4; ks++) mma_bf16(St, aQh[ks], bl[2*ks], bl[2*ks+1]);
#pragma unroll
            for (int ks = 0; ks < 4; ks++) mma_bf16(St, aQl[ks], bh[2*ks], bh[2*ks+1]);
        }

        // ---- mask + scale, tile max ----
        float tm0 = -INFINITY, tm1 = -INFINITY;
#pragma unroll
        for (int tt = 0; tt < 16; tt++) {
            const int mk = k0 + tt * 8 + cb;
#pragma unroll
            for (int e = 0; e < 2; e++) {
                const int m_ = mk + e;
                bool ok0 = qv0 && (m_ <= q_r0) && (m_ < mlen);
                bool ok1 = qv1 && (m_ <= q_r1) && (m_ < mlen);
                S[4*tt + e]     = ok0 ? S[4*tt + e]     * 0.125f : NEG_INF_F;
                S[4*tt + 2 + e] = ok1 ? S[4*tt + 2 + e] * 0.125f : NEG_INF_F;
            }
            tm0 = fmaxf(tm0, fmaxf(S[4*tt], S[4*tt+1]));
            tm1 = fmaxf(tm1, fmaxf(S[4*tt+2], S[4*tt+3]));
        }
        tm0 = fmaxf(tm0, __shfl_xor_sync(0xffffffffu, tm0, 1));
        tm0 = fmaxf(tm0, __shfl_xor_sync(0xffffffffu, tm0, 2));
        tm1 = fmaxf(tm1, __shfl_xor_sync(0xffffffffu, tm1, 1));
        tm1 = fmaxf(tm1, __shfl_xor_sync(0xffffffffu, tm1, 2));

        const float nm0 = fmaxf(m0, tm0), nm1 = fmaxf(m1, tm1);
        const float f0 = __expf(m0 - nm0), f1 = __expf(m1 - nm1);
        m0 = nm0; m1 = nm1;
        if ((l & 3) == 0) {
            FK[kt * 128 + w * 16 + r0]     = nm0;
            FK[kt * 128 + w * 16 + r0 + 8] = nm1;
        }
#pragma unroll
        for (int td = 0; td < 8; td++) {
            ctx[4*td]   *= f0; ctx[4*td+1] *= f0;
            ctx[4*td+2] *= f1; ctx[4*td+3] *= f1;
        }
        float s0 = 0.f, s1 = 0.f;
#pragma unroll
        for (int i = 0; i < 64; i += 4) {
            S[i]   = __expf(S[i]   - nm0); S[i+1] = __expf(S[i+1] - nm0);
            S[i+2] = __expf(S[i+2] - nm1); S[i+3] = __expf(S[i+3] - nm1);
            s0 += S[i] + S[i+1];
            s1 += S[i+2] + S[i+3];
        }
        l0 = l0 * f0 + s0;
        l1 = l1 * f1 + s1;

        // ---- stream unnormalized P = exp(S - m_kt) ----
#pragma unroll
        for (int tt = 0; tt < 16; tt++) {
            const int mk = k0 + tt * 8 + cb;
            *(float2*)(arow + (size_t)q_r0 * 1024 + mk) = make_float2(S[4*tt], S[4*tt+1]);
            *(float2*)(arow + (size_t)q_r1 * 1024 + mk) = make_float2(S[4*tt+2], S[4*tt+3]);
        }

        // ---- PV: ctx += P @ V ----
#pragma unroll
        for (int kk = 0; kk < 8; kk++) {
            uint32_t aH[4], aL[4];
#pragma unroll
            for (int j = 0; j < 4; j++) {
                float e0 = S[8*kk + 2*j], e1 = S[8*kk + 2*j + 1];
                float h0 = __bfloat162float(__float2bfloat16_rn(e0));
                float h1 = __bfloat162float(__float2bfloat16_rn(e1));
                aH[j] = packbf(h0, h1);
                aL[j] = packbf(e0 - h0, e1 - h1);
            }
#pragma unroll
            for (int tdp = 0; tdp < 4; tdp++) {
                uint32_t vh[4], vl[4];
                uint32_t base = (kk * 16 + (l & 15)) * 128 + tdp * 32 + (l >> 4) * 16;
                ldsm4t(vh, sc + 32768 + SWZ(base));
                ldsm4t(vl, sc + 49152 + SWZ(base));
                float* c0 = ctx + 4 * (2 * tdp);
                float* c1 = ctx + 4 * (2 * tdp + 1);
                mma_bf16(c0, aH, vh[0], vh[1]); mma_bf16(c1, aH, vh[2], vh[3]);
                mma_bf16(c0, aH, vl[0], vl[1]); mma_bf16(c1, aH, vl[2], vl[3]);
                mma_bf16(c0, aL, vh[0], vh[1]); mma_bf16(c1, aL, vh[2], vh[3]);
            }
        }
        __syncthreads();
    }

    // ---- finalize: reduce l, write ctx (Vmean for fully-masked rows) ----
    l0 += __shfl_xor_sync(0xffffffffu, l0, 1);
    l0 += __shfl_xor_sync(0xffffffffu, l0, 2);
    l1 += __shfl_xor_sync(0xffffffffu, l1, 1);
    l1 += __shfl_xor_sync(0xffffffffu, l1, 2);
    const float i0 = 1.0f / l0, i1 = 1.0f / l1;
    const float* vm = g_Vmean + (b * 8 + h) * 64;
#pragma unroll
    for (int td = 0; td < 8; td++) {
        int d = td * 8 + cb;
        float2 v0 = qv0 ? make_float2(ctx[4*td] * i0, ctx[4*td+1] * i0)
                        : make_float2(vm[d], vm[d + 1]);
        float2 v1 = qv1 ? make_float2(ctx[4*td+2] * i1, ctx[4*td+3] * i1)
                        : make_float2(vm[d], vm[d + 1]);
        *(float2*)(ctx_out + (size_t)(b * 1024 + q_r0) * 512 + h * 64 + d) = v0;
        *(float2*)(ctx_out + (size_t)(b * 1024 + q_r1) * 512 + h * 64 + d) = v1;
    }

    // ---- epilogue: factor table, then normalize/constant-fill pass ----
    if ((l & 3) == 0) {
        ((float*)(sm + ARM))[w * 16 + r0]     = m0;
        ((float*)(sm + ARM))[w * 16 + r0 + 8] = m1;
        ((float*)(sm + ARI))[w * 16 + r0]     = i0;
        ((float*)(sm + ARI))[w * 16 + r0 + 8] = i1;
    }
    __syncthreads();
    {
        const float* RM = (const float*)(sm + ARM);
        const float* RI = (const float*)(sm + ARI);
#pragma unroll
        for (int i = 0; i < 4; i++) {
            int e = t * 4 + i;
            int ktt = e >> 7, row = e & 127;
            if (ktt < nvt)
                FK[ktt * 128 + row] = __expf(FK[ktt * 128 + row] - RM[row]) * RI[row];
        }
    }
    __syncthreads();
#pragma unroll 4
    for (int it = 0; it < 128; it++) {
        int idx = it * 256 + t;
        int row = idx >> 8, c4 = idx & 255;
        float* p = arow + (size_t)(q0 + row) * 1024 + c4 * 4;
        const int ct = c4 >> 5;
        const bool rv = (q0 + row) < qlen;
        if (!rv) {
            *(float4*)p = make_float4(INV1024, INV1024, INV1024, INV1024);
        } else if (ct < nvt) {
            const float f = FK[ct * 128 + row];
            float4 v = *(float4*)p;
            v.x *= f; v.y *= f; v.z *= f; v.w *= f;
            *(float4*)p = v;
        } else {
            *(float4*)p = make_float4(0.f, 0.f, 0.f, 0.f);
        }
    }
}

// ---------------------------------------------------------------------------
extern "C" void kernel_launch(void* const* d_in, const int* in_sizes, int n_in,
                              void* d_out, int out_size) {
    const float* inputs = (const float*)d_in[0];
    const float* memory = (const float*)d_in[1];
    const float* Wq     = (const float*)d_in[2];
    const float* Wk     = (const float*)d_in[3];
    const float* Wv     = (const float*)d_in[4];
    const int*   mlen   = (const int*)d_in[5];
    const int*   qlen   = (const int*)d_in[6];

    float* out   = (float*)d_out;
    float* ctx   = out;
    float* align = out + (size_t)8 * 1024 * 512;

    cudaFuncSetAttribute(proj_mma, cudaFuncAttributeMaxDynamicSharedMemorySize, P_SMEM);
    cudaFuncSetAttribute(attn_mma, cudaFuncAttributeMaxDynamicSharedMemorySize, A_SMEM);

    split2_k<<<dim3(NELEM / 1024, 2), 256>>>(inputs, memory);
    wsplit_t<<<dim3(8, 8, 3), 256>>>(Wq, Wk, Wv);

    proj_mma<<<dim3(4, 64, 3), 256, P_SMEM>>>();

    vmean_k<<<64, 256>>>();

    attn_mma<<<dim3(8, 8, 8), 256, A_SMEM>>>(mlen, qlen, ctx, align);
}